// round 1
// baseline (speedup 1.0000x reference)
#include <cuda_runtime.h>
#include <cuda_bf16.h>
#include <math.h>

#define TT  2048   // tokens
#define DD  1024   // model dim
#define HH  512    // routed expert hidden
#define HSS 1024   // shared expert hidden
#define EE  8      // experts

// ---------------- scratch (device globals; no allocation allowed) -----------
__device__ int   g_cnt[EE];
__device__ int   g_tok[EE * TT];
__device__ float g_wt [EE * TT];
__device__ float g_hid[(size_t)EE * TT * HH];   // routed GLU hidden, 33.5 MB
__device__ float g_hs [(size_t)TT * HSS];       // shared GLU hidden,  8.4 MB

// ---------------- init: zero expert counts ----------------------------------
__global__ void init_kernel() {
    if (threadIdx.x < EE) g_cnt[threadIdx.x] = 0;
}

// ---------------- router: sigmoid gate, top-2, normalize, bucket ------------
__global__ void router_kernel(const float* __restrict__ x,
                              const float* __restrict__ gw) {
    int warp = (blockIdx.x * blockDim.x + threadIdx.x) >> 5;
    int lane = threadIdx.x & 31;
    if (warp >= TT) return;
    const float* xr = x + (size_t)warp * DD;
    float acc[EE];
    #pragma unroll
    for (int e = 0; e < EE; e++) acc[e] = 0.f;
    for (int d = lane; d < DD; d += 32) {
        float xv = xr[d];
        const float* g = gw + (size_t)d * EE;
        #pragma unroll
        for (int e = 0; e < EE; e++) acc[e] += xv * g[e];
    }
    #pragma unroll
    for (int e = 0; e < EE; e++) {
        #pragma unroll
        for (int o = 16; o > 0; o >>= 1)
            acc[e] += __shfl_xor_sync(0xFFFFFFFFu, acc[e], o);
    }
    if (lane == 0) {
        float s[EE];
        #pragma unroll
        for (int e = 0; e < EE; e++) s[e] = 1.f / (1.f + expf(-acc[e]));
        int i0 = 0;
        #pragma unroll
        for (int e = 1; e < EE; e++) if (s[e] > s[i0]) i0 = e;
        int i1 = (i0 == 0) ? 1 : 0;
        #pragma unroll
        for (int e = 0; e < EE; e++) {
            if (e == i0) continue;
            if (s[e] > s[i1]) i1 = e;
        }
        float sum = s[i0] + s[i1];
        float w0 = s[i0] / sum, w1 = s[i1] / sum;
        int p0 = atomicAdd(&g_cnt[i0], 1);
        g_tok[i0 * TT + p0] = warp; g_wt[i0 * TT + p0] = w0;
        int p1 = atomicAdd(&g_cnt[i1], 1);
        g_tok[i1 * TT + p1] = warp; g_wt[i1 * TT + p1] = w1;
    }
}

__device__ __forceinline__ float silu(float v) {
    return v * (1.f / (1.f + expf(-v)));
}

// ---------------- fused GLU GEMM: C = silu(A@B1) * (A@B3) -------------------
// BM=128, BN=64, BK=16; 256 threads; thread tile 8x4 (dual accumulators).
// GATHER=false: A=x direct, writes g_hs  (N=HSS, K=DD)
// GATHER=true:  A=x rows via g_tok[e],   writes g_hid[e] (N=HH, K=DD), e=blockIdx.z
template<bool GATHER>
__global__ __launch_bounds__(256, 2)
void gemm_glu_kernel(const float* __restrict__ A,
                     const float* __restrict__ B1all,
                     const float* __restrict__ B3all,
                     int N, int Kd) {
    int e = GATHER ? blockIdx.z : 0;
    int M;
    const int* tok = nullptr;
    const float* B1 = B1all;
    const float* B3 = B3all;
    float* C;
    if (GATHER) {
        M = g_cnt[e];
        tok = g_tok + e * TT;
        B1 = B1all + (size_t)e * Kd * N;
        B3 = B3all + (size_t)e * Kd * N;
        C  = g_hid + (size_t)e * TT * N;
    } else {
        M = TT;
        C = g_hs;
    }

    int m0 = blockIdx.y * 128;
    int n0 = blockIdx.x * 64;
    if (m0 >= M) return;

    __shared__ float As [16][128];
    __shared__ float Bs1[16][64];
    __shared__ float Bs3[16][64];

    int tid = threadIdx.x;
    int tx = tid & 15;    // n
    int ty = tid >> 4;    // m

    float acc1[8][4], acc3[8][4];
    #pragma unroll
    for (int i = 0; i < 8; i++)
        #pragma unroll
        for (int j = 0; j < 4; j++) { acc1[i][j] = 0.f; acc3[i][j] = 0.f; }

    // A tile: 128x16 = 512 float4; thread loads f=tid and f+256
    int am0 = tid >> 2;          // 0..63
    int am1 = am0 + 64;
    int ak  = (tid & 3) * 4;
    int r0 = m0 + am0, r1 = m0 + am1;
    bool v0 = r0 < M, v1 = r1 < M;
    int t0, t1;
    if (GATHER) { t0 = v0 ? tok[r0] : 0; t1 = v1 ? tok[r1] : 0; }
    else        { t0 = v0 ? r0 : 0;      t1 = v1 ? r1 : 0; }
    const float* arow0 = A + (size_t)t0 * Kd;
    const float* arow1 = A + (size_t)t1 * Kd;

    // B tile: 16x64 = 256 float4
    int bk = tid >> 4;            // 0..15
    int bn = (tid & 15) * 4;

    for (int k0 = 0; k0 < Kd; k0 += 16) {
        float4 a0 = v0 ? *(const float4*)(arow0 + k0 + ak) : make_float4(0, 0, 0, 0);
        float4 a1 = v1 ? *(const float4*)(arow1 + k0 + ak) : make_float4(0, 0, 0, 0);
        As[ak + 0][am0] = a0.x; As[ak + 1][am0] = a0.y;
        As[ak + 2][am0] = a0.z; As[ak + 3][am0] = a0.w;
        As[ak + 0][am1] = a1.x; As[ak + 1][am1] = a1.y;
        As[ak + 2][am1] = a1.z; As[ak + 3][am1] = a1.w;
        *(float4*)&Bs1[bk][bn] = *(const float4*)(B1 + (size_t)(k0 + bk) * N + n0 + bn);
        *(float4*)&Bs3[bk][bn] = *(const float4*)(B3 + (size_t)(k0 + bk) * N + n0 + bn);
        __syncthreads();
        #pragma unroll
        for (int k = 0; k < 16; k++) {
            float4 aA = *(const float4*)&As[k][ty * 8];
            float4 aB = *(const float4*)&As[k][ty * 8 + 4];
            float4 b1 = *(const float4*)&Bs1[k][tx * 4];
            float4 b3 = *(const float4*)&Bs3[k][tx * 4];
            float a[8] = {aA.x, aA.y, aA.z, aA.w, aB.x, aB.y, aB.z, aB.w};
            float f1[4] = {b1.x, b1.y, b1.z, b1.w};
            float f3[4] = {b3.x, b3.y, b3.z, b3.w};
            #pragma unroll
            for (int i = 0; i < 8; i++)
                #pragma unroll
                for (int j = 0; j < 4; j++) {
                    acc1[i][j] += a[i] * f1[j];
                    acc3[i][j] += a[i] * f3[j];
                }
        }
        __syncthreads();
    }

    #pragma unroll
    for (int i = 0; i < 8; i++) {
        int m = m0 + ty * 8 + i;
        if (m >= M) continue;
        float* crow = C + (size_t)m * N + n0 + tx * 4;
        #pragma unroll
        for (int j = 0; j < 4; j++)
            crow[j] = silu(acc1[i][j]) * acc3[i][j];
    }
}

// ---------------- single GEMM: C = A@B ---------------------------------------
// BM=128, BN=128, BK=16; 256 threads; thread tile 8x8 (split-n for bank safety)
// SCATTER=false: A=g_hs, B=ws2, plain store to out   (N=DD, K=HSS)
// SCATTER=true : A=g_hid[e], B=w2[e], atomicAdd wt*val into out (N=DD, K=HH)
template<bool SCATTER>
__global__ __launch_bounds__(256, 2)
void gemm_single_kernel(const float* __restrict__ Ball,
                        float* __restrict__ out,
                        int N, int Kd) {
    int e = SCATTER ? blockIdx.z : 0;
    int M;
    const float* A;
    const float* B;
    const int* tok = nullptr;
    const float* wt = nullptr;
    if (SCATTER) {
        M = g_cnt[e];
        A = g_hid + (size_t)e * TT * HH;
        B = Ball + (size_t)e * Kd * N;
        tok = g_tok + e * TT;
        wt  = g_wt  + e * TT;
    } else {
        M = TT;
        A = g_hs;
        B = Ball;
    }

    int m0 = blockIdx.y * 128;
    int n0 = blockIdx.x * 128;
    if (m0 >= M) return;

    __shared__ float As[16][128];
    __shared__ float Bs[16][128];

    int tid = threadIdx.x;
    int tx = tid & 15;
    int ty = tid >> 4;

    float acc[8][8];
    #pragma unroll
    for (int i = 0; i < 8; i++)
        #pragma unroll
        for (int j = 0; j < 8; j++) acc[i][j] = 0.f;

    int am0 = tid >> 2;
    int am1 = am0 + 64;
    int ak  = (tid & 3) * 4;
    int r0 = m0 + am0, r1 = m0 + am1;
    bool v0 = r0 < M, v1 = r1 < M;
    const float* arow0 = A + (size_t)(v0 ? r0 : 0) * Kd;
    const float* arow1 = A + (size_t)(v1 ? r1 : 0) * Kd;

    int bk = tid >> 5;            // 0..7 (+8 for second load)
    int bn = (tid & 31) * 4;

    for (int k0 = 0; k0 < Kd; k0 += 16) {
        float4 a0 = v0 ? *(const float4*)(arow0 + k0 + ak) : make_float4(0, 0, 0, 0);
        float4 a1 = v1 ? *(const float4*)(arow1 + k0 + ak) : make_float4(0, 0, 0, 0);
        As[ak + 0][am0] = a0.x; As[ak + 1][am0] = a0.y;
        As[ak + 2][am0] = a0.z; As[ak + 3][am0] = a0.w;
        As[ak + 0][am1] = a1.x; As[ak + 1][am1] = a1.y;
        As[ak + 2][am1] = a1.z; As[ak + 3][am1] = a1.w;
        *(float4*)&Bs[bk][bn]     = *(const float4*)(B + (size_t)(k0 + bk) * N + n0 + bn);
        *(float4*)&Bs[bk + 8][bn] = *(const float4*)(B + (size_t)(k0 + bk + 8) * N + n0 + bn);
        __syncthreads();
        #pragma unroll
        for (int k = 0; k < 16; k++) {
            float4 aA = *(const float4*)&As[k][ty * 8];
            float4 aB = *(const float4*)&As[k][ty * 8 + 4];
            float4 b0 = *(const float4*)&Bs[k][tx * 4];        // n block 0
            float4 b1 = *(const float4*)&Bs[k][64 + tx * 4];   // n block 1
            float a[8] = {aA.x, aA.y, aA.z, aA.w, aB.x, aB.y, aB.z, aB.w};
            float bb[8] = {b0.x, b0.y, b0.z, b0.w, b1.x, b1.y, b1.z, b1.w};
            #pragma unroll
            for (int i = 0; i < 8; i++)
                #pragma unroll
                for (int j = 0; j < 8; j++)
                    acc[i][j] += a[i] * bb[j];
        }
        __syncthreads();
    }

    #pragma unroll
    for (int i = 0; i < 8; i++) {
        int m = m0 + ty * 8 + i;
        if (m >= M) continue;
        if (SCATTER) {
            int t = tok[m];
            float w = wt[m];
            float* orow = out + (size_t)t * N;
            #pragma unroll
            for (int j = 0; j < 4; j++)
                atomicAdd(&orow[n0 + tx * 4 + j], w * acc[i][j]);
            #pragma unroll
            for (int j = 0; j < 4; j++)
                atomicAdd(&orow[n0 + 64 + tx * 4 + j], w * acc[i][j + 4]);
        } else {
            float* orow = out + (size_t)m * N;
            #pragma unroll
            for (int j = 0; j < 4; j++)
                orow[n0 + tx * 4 + j] = acc[i][j];
            #pragma unroll
            for (int j = 0; j < 4; j++)
                orow[n0 + 64 + tx * 4 + j] = acc[i][j + 4];
        }
    }
}

// ---------------- launch -----------------------------------------------------
extern "C" void kernel_launch(void* const* d_in, const int* in_sizes, int n_in,
                              void* d_out, int out_size) {
    const float* x   = (const float*)d_in[0];
    const float* gw  = (const float*)d_in[1];
    const float* w1  = (const float*)d_in[2];
    const float* w3  = (const float*)d_in[3];
    const float* w2  = (const float*)d_in[4];
    const float* ws1 = (const float*)d_in[5];
    const float* ws3 = (const float*)d_in[6];
    const float* ws2 = (const float*)d_in[7];
    float* out = (float*)d_out;

    init_kernel<<<1, 32>>>();
    router_kernel<<<TT / 8, 256>>>(x, gw);

    // shared expert: GLU then down-proj (plain store establishes out base)
    {
        dim3 g(HSS / 64, TT / 128, 1);
        gemm_glu_kernel<false><<<g, 256>>>(x, ws1, ws3, HSS, DD);
    }
    {
        dim3 g(DD / 128, TT / 128, 1);
        gemm_single_kernel<false><<<g, 256>>>(ws2, out, DD, HSS);
    }

    // routed experts: gathered GLU, then weighted atomic scatter down-proj
    {
        dim3 g(HH / 64, TT / 128, EE);
        gemm_glu_kernel<true><<<g, 256>>>(x, w1, w3, HH, DD);
    }
    {
        dim3 g(DD / 128, TT / 128, EE);
        gemm_single_kernel<true><<<g, 256>>>(w2, out, DD, HH);
    }
}